// round 15
// baseline (speedup 1.0000x reference)
#include <cuda_runtime.h>
#include <cuda_bf16.h>

// Problem constants (fixed shapes from reference)
#define NMAX   100000
#define EMAX   3200000
#define NFEAT  512
#define NHID   8
#define NCLASS 16

// ---------------- scratch (device globals; no allocation allowed) ----------
__device__ float g_supp1[NMAX * NHID];    // x @ W1
__device__ float g_xr   [NMAX * NHID];    // gamma*relu(0.5*(xv^2 - x2v2))+beta
__device__ float g_supp2[NMAX * NCLASS];  // h @ W2
__device__ int   g_cnt     [NMAX];        // row degree
__device__ int   g_rowstart[NMAX];        // CSR row start
__device__ int   g_fill    [NMAX];        // scatter cursor
__device__ int   g_bsum[256];             // scan block sums
__device__ int   g_boff[256];             // scanned block offsets
__device__ int2  g_epack[EMAX];           // packed (col, val-bits) per edge, CSR order

// ---------------- f32x2 packed-math helpers (Blackwell) --------------------
__device__ __forceinline__ unsigned long long pk2(float a, float b) {
    unsigned long long r;
    asm("mov.b64 %0, {%1, %2};" : "=l"(r) : "f"(a), "f"(b));
    return r;
}
__device__ __forceinline__ unsigned long long ffma2(unsigned long long a,
                                                    unsigned long long b,
                                                    unsigned long long c) {
    unsigned long long d;
    asm("fma.rn.f32x2 %0, %1, %2, %3;" : "=l"(d) : "l"(a), "l"(b), "l"(c));
    return d;
}
__device__ __forceinline__ void upk2(unsigned long long v, float& a, float& b) {
    asm("mov.b64 {%0, %1}, %2;" : "=f"(a), "=f"(b) : "l"(v));
}

// ---------------- kernel 1: fused node transform (unchanged, works) --------
#define KT 32
#define K1_WARPS 8
#define K1_SX_STRIDE 33
#define K1_SMEM_FLOATS (3 * NFEAT * NHID + K1_WARPS * 32 * K1_SX_STRIDE + 16)

__global__ void __launch_bounds__(256)
k1_transform(const float* __restrict__ x,
             const float* __restrict__ W1,
             const float* __restrict__ V,
             const float* __restrict__ gamma,
             const float* __restrict__ beta,
             int n)
{
    extern __shared__ __align__(16) float sm[];
    float* sW1 = sm;
    float* sV  = sm + NFEAT * NHID;
    float* sV2 = sm + 2 * NFEAT * NHID;
    float* sx  = sm + 3 * NFEAT * NHID;
    float* sgb = sx + K1_WARPS * 32 * K1_SX_STRIDE;

    int tid = threadIdx.x;
    for (int i = tid; i < NFEAT * NHID; i += blockDim.x) {
        float w = W1[i];  sW1[i] = w;
        float v = V[i];   sV[i]  = v;  sV2[i] = v * v;
    }
    if (tid < NHID) { sgb[tid] = gamma[tid]; sgb[NHID + tid] = beta[tid]; }
    __syncthreads();

    const int warp = tid >> 5, lane = tid & 31;
    float* sxw = sx + warp * (32 * K1_SX_STRIDE);
    const int nodeBase = blockIdx.x * 256 + warp * 32;
    const int myNode = nodeBase + lane;

    const ulonglong2* pW1 = reinterpret_cast<const ulonglong2*>(sW1);
    const ulonglong2* pV  = reinterpret_cast<const ulonglong2*>(sV);
    const ulonglong2* pQ  = reinterpret_cast<const ulonglong2*>(sV2);

    unsigned long long aW[4] = {0ull, 0ull, 0ull, 0ull};
    unsigned long long aX[4] = {0ull, 0ull, 0ull, 0ull};
    unsigned long long aQ[4] = {0ull, 0ull, 0ull, 0ull};

    const int r0 = lane >> 3;
    const int c0 = (lane & 7) * 4;

#pragma unroll 1
    for (int kt = 0; kt < NFEAT; kt += KT) {
#pragma unroll
        for (int i = 0; i < 8; i++) {
            int row = r0 + i * 4;
            int node = nodeBase + row;
            if (node >= n) node = n - 1;
            float4 v4 = *reinterpret_cast<const float4*>(x + (size_t)node * NFEAT + kt + c0);
            float* d = sxw + row * K1_SX_STRIDE + c0;
            d[0] = v4.x; d[1] = v4.y; d[2] = v4.z; d[3] = v4.w;
        }
        __syncwarp();
        const float* myx = sxw + lane * K1_SX_STRIDE;
#pragma unroll
        for (int kk = 0; kk < KT; kk++) {
            float xv = myx[kk];
            float x2 = xv * xv;
            unsigned long long xp  = pk2(xv, xv);
            unsigned long long x2p = pk2(x2, x2);
            int k2 = (kt + kk) * 2;
            ulonglong2 wa = pW1[k2], wb = pW1[k2 + 1];
            aW[0] = ffma2(xp, wa.x, aW[0]);  aW[1] = ffma2(xp, wa.y, aW[1]);
            aW[2] = ffma2(xp, wb.x, aW[2]);  aW[3] = ffma2(xp, wb.y, aW[3]);
            ulonglong2 va = pV[k2],  vb = pV[k2 + 1];
            aX[0] = ffma2(xp, va.x, aX[0]);  aX[1] = ffma2(xp, va.y, aX[1]);
            aX[2] = ffma2(xp, vb.x, aX[2]);  aX[3] = ffma2(xp, vb.y, aX[3]);
            ulonglong2 qa = pQ[k2],  qb = pQ[k2 + 1];
            aQ[0] = ffma2(x2p, qa.x, aQ[0]); aQ[1] = ffma2(x2p, qa.y, aQ[1]);
            aQ[2] = ffma2(x2p, qb.x, aQ[2]); aQ[3] = ffma2(x2p, qb.y, aQ[3]);
        }
        __syncwarp();
    }

    if (myNode < n) {
        float o[8], xvv[8], qq[8];
        upk2(aW[0], o[0], o[1]);   upk2(aW[1], o[2], o[3]);
        upk2(aW[2], o[4], o[5]);   upk2(aW[3], o[6], o[7]);
        upk2(aX[0], xvv[0], xvv[1]); upk2(aX[1], xvv[2], xvv[3]);
        upk2(aX[2], xvv[4], xvv[5]); upk2(aX[3], xvv[6], xvv[7]);
        upk2(aQ[0], qq[0], qq[1]);   upk2(aQ[1], qq[2], qq[3]);
        upk2(aQ[2], qq[4], qq[5]);   upk2(aQ[3], qq[6], qq[7]);

        float4* ds = reinterpret_cast<float4*>(g_supp1 + (size_t)myNode * NHID);
        ds[0] = make_float4(o[0], o[1], o[2], o[3]);
        ds[1] = make_float4(o[4], o[5], o[6], o[7]);

        float xr[8];
#pragma unroll
        for (int j = 0; j < NHID; j++) {
            float t = 0.5f * (xvv[j] * xvv[j] - qq[j]);
            t = fmaxf(t, 0.f);
            xr[j] = sgb[j] * t + sgb[NHID + j];
        }
        float4* dr = reinterpret_cast<float4*>(g_xr + (size_t)myNode * NHID);
        dr[0] = make_float4(xr[0], xr[1], xr[2], xr[3]);
        dr[1] = make_float4(xr[4], xr[5], xr[6], xr[7]);
    }
}

// ---------------- CSR construction ------------------------------------------
__global__ void k_zero_cnt(int n) {
    int i = blockIdx.x * blockDim.x + threadIdx.x;
    if (i < n) g_cnt[i] = 0;
}

__global__ void k_hist(const int* __restrict__ rows, int e) {
    int i = blockIdx.x * blockDim.x + threadIdx.x;
    if (i < e) atomicAdd(&g_cnt[rows[i]], 1);
}

// block-level scan (512 elems per block)
__global__ void __launch_bounds__(512) k_scanA(int n) {
    __shared__ int sh[512];
    int t = threadIdx.x;
    int i = blockIdx.x * 512 + t;
    int c = (i < n) ? g_cnt[i] : 0;
    sh[t] = c;
    __syncthreads();
    int val = c;
#pragma unroll
    for (int off = 1; off < 512; off <<= 1) {
        int tt = (t >= off) ? sh[t - off] : 0;
        __syncthreads();
        val += tt;
        sh[t] = val;
        __syncthreads();
    }
    if (i < n) g_rowstart[i] = val - c;   // exclusive, block-local
    if (t == 511) g_bsum[blockIdx.x] = val;
}

__global__ void __launch_bounds__(256) k_scanB(int nb) {
    __shared__ int sh[256];
    int t = threadIdx.x;
    int c = (t < nb) ? g_bsum[t] : 0;
    sh[t] = c;
    __syncthreads();
    int val = c;
#pragma unroll
    for (int off = 1; off < 256; off <<= 1) {
        int tt = (t >= off) ? sh[t - off] : 0;
        __syncthreads();
        val += tt;
        sh[t] = val;
        __syncthreads();
    }
    if (t < nb) g_boff[t] = val - c;      // exclusive block offsets
}

__global__ void k_scanC(int n) {
    int i = blockIdx.x * blockDim.x + threadIdx.x;
    if (i >= n) return;
    int s = g_rowstart[i] + g_boff[i >> 9];
    g_rowstart[i] = s;
    g_fill[i] = s;
}

__global__ void k_scatter(const int* __restrict__ rows,
                          const int* __restrict__ cols,
                          const float* __restrict__ vals, int e) {
    int i = blockIdx.x * blockDim.x + threadIdx.x;
    if (i >= e) return;
    int r = rows[i];
    int idx = atomicAdd(&g_fill[r], 1);
    g_epack[idx] = make_int2(cols[i], __float_as_int(vals[i]));
}

// ---------------- fused spmm1 + mid (thread per row, CSR, no atomics) ------
__global__ void __launch_bounds__(256)
k_spmm1mid(const float* __restrict__ b1, const float* __restrict__ W2, int n)
{
    __shared__ float sW2[NHID * NCLASS];
    __shared__ float sb1[NHID];
    if (threadIdx.x < NHID * NCLASS) sW2[threadIdx.x] = W2[threadIdx.x];
    if (threadIdx.x < NHID)          sb1[threadIdx.x] = b1[threadIdx.x];
    __syncthreads();
    int r = blockIdx.x * blockDim.x + threadIdx.x;
    if (r >= n) return;

    const int start = g_rowstart[r];
    const int deg   = g_cnt[r];
    const int2* ep  = g_epack + start;

    float4 A0 = make_float4(0.f, 0.f, 0.f, 0.f), A1 = A0;

    int j = 0;
    for (; j + 4 <= deg; j += 4) {
        int2 p0 = ep[j], p1 = ep[j + 1], p2 = ep[j + 2], p3 = ep[j + 3];
        const float4* s0 = reinterpret_cast<const float4*>(g_supp1 + (size_t)p0.x * NHID);
        const float4* s1 = reinterpret_cast<const float4*>(g_supp1 + (size_t)p1.x * NHID);
        const float4* s2 = reinterpret_cast<const float4*>(g_supp1 + (size_t)p2.x * NHID);
        const float4* s3 = reinterpret_cast<const float4*>(g_supp1 + (size_t)p3.x * NHID);
        float4 a0 = s0[0], c0 = s0[1];
        float4 a1 = s1[0], c1 = s1[1];
        float4 a2 = s2[0], c2 = s2[1];
        float4 a3 = s3[0], c3 = s3[1];
        float v0 = __int_as_float(p0.y), v1 = __int_as_float(p1.y);
        float v2 = __int_as_float(p2.y), v3 = __int_as_float(p3.y);
        A0.x = fmaf(v0, a0.x, A0.x); A0.y = fmaf(v0, a0.y, A0.y);
        A0.z = fmaf(v0, a0.z, A0.z); A0.w = fmaf(v0, a0.w, A0.w);
        A1.x = fmaf(v0, c0.x, A1.x); A1.y = fmaf(v0, c0.y, A1.y);
        A1.z = fmaf(v0, c0.z, A1.z); A1.w = fmaf(v0, c0.w, A1.w);
        A0.x = fmaf(v1, a1.x, A0.x); A0.y = fmaf(v1, a1.y, A0.y);
        A0.z = fmaf(v1, a1.z, A0.z); A0.w = fmaf(v1, a1.w, A0.w);
        A1.x = fmaf(v1, c1.x, A1.x); A1.y = fmaf(v1, c1.y, A1.y);
        A1.z = fmaf(v1, c1.z, A1.z); A1.w = fmaf(v1, c1.w, A1.w);
        A0.x = fmaf(v2, a2.x, A0.x); A0.y = fmaf(v2, a2.y, A0.y);
        A0.z = fmaf(v2, a2.z, A0.z); A0.w = fmaf(v2, a2.w, A0.w);
        A1.x = fmaf(v2, c2.x, A1.x); A1.y = fmaf(v2, c2.y, A1.y);
        A1.z = fmaf(v2, c2.z, A1.z); A1.w = fmaf(v2, c2.w, A1.w);
        A0.x = fmaf(v3, a3.x, A0.x); A0.y = fmaf(v3, a3.y, A0.y);
        A0.z = fmaf(v3, a3.z, A0.z); A0.w = fmaf(v3, a3.w, A0.w);
        A1.x = fmaf(v3, c3.x, A1.x); A1.y = fmaf(v3, c3.y, A1.y);
        A1.z = fmaf(v3, c3.z, A1.z); A1.w = fmaf(v3, c3.w, A1.w);
    }
    for (; j < deg; j++) {
        int2 p = ep[j];
        const float4* s = reinterpret_cast<const float4*>(g_supp1 + (size_t)p.x * NHID);
        float4 a = s[0], c = s[1];
        float v = __int_as_float(p.y);
        A0.x = fmaf(v, a.x, A0.x); A0.y = fmaf(v, a.y, A0.y);
        A0.z = fmaf(v, a.z, A0.z); A0.w = fmaf(v, a.w, A0.w);
        A1.x = fmaf(v, c.x, A1.x); A1.y = fmaf(v, c.y, A1.y);
        A1.z = fmaf(v, c.z, A1.z); A1.w = fmaf(v, c.w, A1.w);
    }

    // epilogue: bias + relu + combine with xr + h@W2
    float ag[8] = {A0.x, A0.y, A0.z, A0.w, A1.x, A1.y, A1.z, A1.w};
    const float4* xr4 = reinterpret_cast<const float4*>(g_xr + (size_t)r * NHID);
    float4 x0 = xr4[0], x1 = xr4[1];
    float xr[8] = {x0.x, x0.y, x0.z, x0.w, x1.x, x1.y, x1.z, x1.w};

    float h[8];
#pragma unroll
    for (int k = 0; k < NHID; k++) {
        float t = fmaxf(ag[k] + sb1[k], 0.f);
        h[k] = 0.5f * (t + xr[k]);
    }
    float acc[NCLASS];
#pragma unroll
    for (int q = 0; q < NCLASS; q++) acc[q] = 0.f;
#pragma unroll
    for (int k = 0; k < NHID; k++) {
        float hk = h[k];
#pragma unroll
        for (int q = 0; q < NCLASS; q++) acc[q] = fmaf(hk, sW2[k * NCLASS + q], acc[q]);
    }
    float4* o = reinterpret_cast<float4*>(g_supp2 + (size_t)r * NCLASS);
    o[0] = make_float4(acc[0],  acc[1],  acc[2],  acc[3]);
    o[1] = make_float4(acc[4],  acc[5],  acc[6],  acc[7]);
    o[2] = make_float4(acc[8],  acc[9],  acc[10], acc[11]);
    o[3] = make_float4(acc[12], acc[13], acc[14], acc[15]);
}

// ---------------- fused spmm2 + bias + log_softmax (thread per row) --------
__global__ void __launch_bounds__(256)
k_spmm2final(const float* __restrict__ b2, float* __restrict__ out, int n)
{
    __shared__ float sb2[NCLASS];
    if (threadIdx.x < NCLASS) sb2[threadIdx.x] = b2[threadIdx.x];
    __syncthreads();
    int r = blockIdx.x * blockDim.x + threadIdx.x;
    if (r >= n) return;

    const int start = g_rowstart[r];
    const int deg   = g_cnt[r];
    const int2* ep  = g_epack + start;

    float4 A0 = make_float4(0.f, 0.f, 0.f, 0.f), A1 = A0, A2 = A0, A3 = A0;

    int j = 0;
    for (; j + 2 <= deg; j += 2) {
        int2 p0 = ep[j], p1 = ep[j + 1];
        const float4* s0 = reinterpret_cast<const float4*>(g_supp2 + (size_t)p0.x * NCLASS);
        const float4* s1 = reinterpret_cast<const float4*>(g_supp2 + (size_t)p1.x * NCLASS);
        float4 a0 = s0[0], a1 = s0[1], a2 = s0[2], a3 = s0[3];
        float4 c0 = s1[0], c1 = s1[1], c2 = s1[2], c3 = s1[3];
        float v0 = __int_as_float(p0.y), v1 = __int_as_float(p1.y);
        A0.x = fmaf(v0, a0.x, A0.x); A0.y = fmaf(v0, a0.y, A0.y);
        A0.z = fmaf(v0, a0.z, A0.z); A0.w = fmaf(v0, a0.w, A0.w);
        A1.x = fmaf(v0, a1.x, A1.x); A1.y = fmaf(v0, a1.y, A1.y);
        A1.z = fmaf(v0, a1.z, A1.z); A1.w = fmaf(v0, a1.w, A1.w);
        A2.x = fmaf(v0, a2.x, A2.x); A2.y = fmaf(v0, a2.y, A2.y);
        A2.z = fmaf(v0, a2.z, A2.z); A2.w = fmaf(v0, a2.w, A2.w);
        A3.x = fmaf(v0, a3.x, A3.x); A3.y = fmaf(v0, a3.y, A3.y);
        A3.z = fmaf(v0, a3.z, A3.z); A3.w = fmaf(v0, a3.w, A3.w);
        A0.x = fmaf(v1, c0.x, A0.x); A0.y = fmaf(v1, c0.y, A0.y);
        A0.z = fmaf(v1, c0.z, A0.z); A0.w = fmaf(v1, c0.w, A0.w);
        A1.x = fmaf(v1, c1.x, A1.x); A1.y = fmaf(v1, c1.y, A1.y);
        A1.z = fmaf(v1, c1.z, A1.z); A1.w = fmaf(v1, c1.w, A1.w);
        A2.x = fmaf(v1, c2.x, A2.x); A2.y = fmaf(v1, c2.y, A2.y);
        A2.z = fmaf(v1, c2.z, A2.z); A2.w = fmaf(v1, c2.w, A2.w);
        A3.x = fmaf(v1, c3.x, A3.x); A3.y = fmaf(v1, c3.y, A3.y);
        A3.z = fmaf(v1, c3.z, A3.z); A3.w = fmaf(v1, c3.w, A3.w);
    }
    for (; j < deg; j++) {
        int2 p = ep[j];
        const float4* s = reinterpret_cast<const float4*>(g_supp2 + (size_t)p.x * NCLASS);
        float4 a0 = s[0], a1 = s[1], a2 = s[2], a3 = s[3];
        float v = __int_as_float(p.y);
        A0.x = fmaf(v, a0.x, A0.x); A0.y = fmaf(v, a0.y, A0.y);
        A0.z = fmaf(v, a0.z, A0.z); A0.w = fmaf(v, a0.w, A0.w);
        A1.x = fmaf(v, a1.x, A1.x); A1.y = fmaf(v, a1.y, A1.y);
        A1.z = fmaf(v, a1.z, A1.z); A1.w = fmaf(v, a1.w, A1.w);
        A2.x = fmaf(v, a2.x, A2.x); A2.y = fmaf(v, a2.y, A2.y);
        A2.z = fmaf(v, a2.z, A2.z); A2.w = fmaf(v, a2.w, A2.w);
        A3.x = fmaf(v, a3.x, A3.x); A3.y = fmaf(v, a3.y, A3.y);
        A3.z = fmaf(v, a3.z, A3.z); A3.w = fmaf(v, a3.w, A3.w);
    }

    float v[NCLASS] = {A0.x, A0.y, A0.z, A0.w, A1.x, A1.y, A1.z, A1.w,
                       A2.x, A2.y, A2.z, A2.w, A3.x, A3.y, A3.z, A3.w};
#pragma unroll
    for (int q = 0; q < NCLASS; q++) v[q] += sb2[q];

    float m = v[0];
#pragma unroll
    for (int q = 1; q < NCLASS; q++) m = fmaxf(m, v[q]);
    float s = 0.f;
#pragma unroll
    for (int q = 0; q < NCLASS; q++) s += expf(v[q] - m);
    float l = m + logf(s);

    float4* o = reinterpret_cast<float4*>(out + (size_t)r * NCLASS);
    o[0] = make_float4(v[0]  - l, v[1]  - l, v[2]  - l, v[3]  - l);
    o[1] = make_float4(v[4]  - l, v[5]  - l, v[6]  - l, v[7]  - l);
    o[2] = make_float4(v[8]  - l, v[9]  - l, v[10] - l, v[11] - l);
    o[3] = make_float4(v[12] - l, v[13] - l, v[14] - l, v[15] - l);
}

// ---------------- launch ----------------------------------------------------
extern "C" void kernel_launch(void* const* d_in, const int* in_sizes, int n_in,
                              void* d_out, int out_size)
{
    const float* x        = (const float*)d_in[0];
    const int*   adj_rows = (const int*)  d_in[1];
    const int*   adj_cols = (const int*)  d_in[2];
    const float* adj_vals = (const float*)d_in[3];
    const float* W1       = (const float*)d_in[4];
    const float* b1       = (const float*)d_in[5];
    const float* W2       = (const float*)d_in[6];
    const float* b2       = (const float*)d_in[7];
    const float* V        = (const float*)d_in[8];
    const float* gamma    = (const float*)d_in[9];
    const float* beta     = (const float*)d_in[10];
    float* out = (float*)d_out;

    const int n = in_sizes[0] / NFEAT;
    const int e = in_sizes[1];

    const int smem1 = K1_SMEM_FLOATS * (int)sizeof(float);
    cudaFuncSetAttribute(k1_transform, cudaFuncAttributeMaxDynamicSharedMemorySize, smem1);

    const int nbScan = (n + 511) / 512;   // <= 256 required (100000/512 = 196)

    // CSR build
    k_zero_cnt<<<(n + 255) / 256, 256>>>(n);
    k_hist<<<(e + 255) / 256, 256>>>(adj_rows, e);
    k_scanA<<<nbScan, 512>>>(n);
    k_scanB<<<1, 256>>>(nbScan);
    k_scanC<<<(n + 255) / 256, 256>>>(n);
    k_scatter<<<(e + 255) / 256, 256>>>(adj_rows, adj_cols, adj_vals, e);

    // node transform (independent of CSR; produces supp1 + xr)
    k1_transform<<<(n + 255) / 256, 256, smem1>>>(x, W1, V, gamma, beta, n);

    // fused spmm1 + mid -> supp2
    k_spmm1mid<<<(n + 255) / 256, 256>>>(b1, W2, n);
    // fused spmm2 + bias + log_softmax -> out
    k_spmm2final<<<(n + 255) / 256, 256>>>(b2, out, n);
}

// round 16
// speedup vs baseline: 1.0782x; 1.0782x over previous
#include <cuda_runtime.h>
#include <cuda_bf16.h>

// Problem constants (fixed shapes from reference)
#define NMAX   100000
#define EMAX   3200000
#define NFEAT  512
#define NHID   8
#define NCLASS 16

// ---------------- scratch (device globals; no allocation allowed) ----------
__device__ float g_supp1[NMAX * NHID];    // x @ W1
__device__ float g_xr   [NMAX * NHID];    // gamma*relu(0.5*(xv^2 - x2v2))+beta
__device__ float g_h    [NMAX * NHID];    // 0.5*(relu(agg1+b1)+xr)  (8-wide!)
__device__ int   g_cnt     [NMAX];        // row degree
__device__ int   g_rowstart[NMAX];        // CSR row start
__device__ int   g_fill    [NMAX];        // scatter cursor
__device__ int   g_bsum[256];             // scan block sums
__device__ int   g_boff[256];             // scanned block offsets
__device__ int2  g_epack[EMAX];           // packed (col, val-bits), CSR order

// ---------------- f32x2 packed-math helpers (Blackwell) --------------------
__device__ __forceinline__ unsigned long long pk2(float a, float b) {
    unsigned long long r;
    asm("mov.b64 %0, {%1, %2};" : "=l"(r) : "f"(a), "f"(b));
    return r;
}
__device__ __forceinline__ unsigned long long ffma2(unsigned long long a,
                                                    unsigned long long b,
                                                    unsigned long long c) {
    unsigned long long d;
    asm("fma.rn.f32x2 %0, %1, %2, %3;" : "=l"(d) : "l"(a), "l"(b), "l"(c));
    return d;
}
__device__ __forceinline__ void upk2(unsigned long long v, float& a, float& b) {
    asm("mov.b64 {%0, %1}, %2;" : "=f"(a), "=f"(b) : "l"(v));
}

// ---------------- kernel 1: fused node transform (unchanged, works) --------
#define KT 32
#define K1_WARPS 8
#define K1_SX_STRIDE 33
#define K1_SMEM_FLOATS (3 * NFEAT * NHID + K1_WARPS * 32 * K1_SX_STRIDE + 16)

__global__ void __launch_bounds__(256)
k1_transform(const float* __restrict__ x,
             const float* __restrict__ W1,
             const float* __restrict__ V,
             const float* __restrict__ gamma,
             const float* __restrict__ beta,
             int n)
{
    extern __shared__ __align__(16) float sm[];
    float* sW1 = sm;
    float* sV  = sm + NFEAT * NHID;
    float* sV2 = sm + 2 * NFEAT * NHID;
    float* sx  = sm + 3 * NFEAT * NHID;
    float* sgb = sx + K1_WARPS * 32 * K1_SX_STRIDE;

    int tid = threadIdx.x;
    for (int i = tid; i < NFEAT * NHID; i += blockDim.x) {
        float w = W1[i];  sW1[i] = w;
        float v = V[i];   sV[i]  = v;  sV2[i] = v * v;
    }
    if (tid < NHID) { sgb[tid] = gamma[tid]; sgb[NHID + tid] = beta[tid]; }
    __syncthreads();

    const int warp = tid >> 5, lane = tid & 31;
    float* sxw = sx + warp * (32 * K1_SX_STRIDE);
    const int nodeBase = blockIdx.x * 256 + warp * 32;
    const int myNode = nodeBase + lane;

    const ulonglong2* pW1 = reinterpret_cast<const ulonglong2*>(sW1);
    const ulonglong2* pV  = reinterpret_cast<const ulonglong2*>(sV);
    const ulonglong2* pQ  = reinterpret_cast<const ulonglong2*>(sV2);

    unsigned long long aW[4] = {0ull, 0ull, 0ull, 0ull};
    unsigned long long aX[4] = {0ull, 0ull, 0ull, 0ull};
    unsigned long long aQ[4] = {0ull, 0ull, 0ull, 0ull};

    const int r0 = lane >> 3;
    const int c0 = (lane & 7) * 4;

#pragma unroll 1
    for (int kt = 0; kt < NFEAT; kt += KT) {
#pragma unroll
        for (int i = 0; i < 8; i++) {
            int row = r0 + i * 4;
            int node = nodeBase + row;
            if (node >= n) node = n - 1;
            float4 v4 = *reinterpret_cast<const float4*>(x + (size_t)node * NFEAT + kt + c0);
            float* d = sxw + row * K1_SX_STRIDE + c0;
            d[0] = v4.x; d[1] = v4.y; d[2] = v4.z; d[3] = v4.w;
        }
        __syncwarp();
        const float* myx = sxw + lane * K1_SX_STRIDE;
#pragma unroll
        for (int kk = 0; kk < KT; kk++) {
            float xv = myx[kk];
            float x2 = xv * xv;
            unsigned long long xp  = pk2(xv, xv);
            unsigned long long x2p = pk2(x2, x2);
            int k2 = (kt + kk) * 2;
            ulonglong2 wa = pW1[k2], wb = pW1[k2 + 1];
            aW[0] = ffma2(xp, wa.x, aW[0]);  aW[1] = ffma2(xp, wa.y, aW[1]);
            aW[2] = ffma2(xp, wb.x, aW[2]);  aW[3] = ffma2(xp, wb.y, aW[3]);
            ulonglong2 va = pV[k2],  vb = pV[k2 + 1];
            aX[0] = ffma2(xp, va.x, aX[0]);  aX[1] = ffma2(xp, va.y, aX[1]);
            aX[2] = ffma2(xp, vb.x, aX[2]);  aX[3] = ffma2(xp, vb.y, aX[3]);
            ulonglong2 qa = pQ[k2],  qb = pQ[k2 + 1];
            aQ[0] = ffma2(x2p, qa.x, aQ[0]); aQ[1] = ffma2(x2p, qa.y, aQ[1]);
            aQ[2] = ffma2(x2p, qb.x, aQ[2]); aQ[3] = ffma2(x2p, qb.y, aQ[3]);
        }
        __syncwarp();
    }

    if (myNode < n) {
        float o[8], xvv[8], qq[8];
        upk2(aW[0], o[0], o[1]);   upk2(aW[1], o[2], o[3]);
        upk2(aW[2], o[4], o[5]);   upk2(aW[3], o[6], o[7]);
        upk2(aX[0], xvv[0], xvv[1]); upk2(aX[1], xvv[2], xvv[3]);
        upk2(aX[2], xvv[4], xvv[5]); upk2(aX[3], xvv[6], xvv[7]);
        upk2(aQ[0], qq[0], qq[1]);   upk2(aQ[1], qq[2], qq[3]);
        upk2(aQ[2], qq[4], qq[5]);   upk2(aQ[3], qq[6], qq[7]);

        float4* ds = reinterpret_cast<float4*>(g_supp1 + (size_t)myNode * NHID);
        ds[0] = make_float4(o[0], o[1], o[2], o[3]);
        ds[1] = make_float4(o[4], o[5], o[6], o[7]);

        float xr[8];
#pragma unroll
        for (int j = 0; j < NHID; j++) {
            float t = 0.5f * (xvv[j] * xvv[j] - qq[j]);
            t = fmaxf(t, 0.f);
            xr[j] = sgb[j] * t + sgb[NHID + j];
        }
        float4* dr = reinterpret_cast<float4*>(g_xr + (size_t)myNode * NHID);
        dr[0] = make_float4(xr[0], xr[1], xr[2], xr[3]);
        dr[1] = make_float4(xr[4], xr[5], xr[6], xr[7]);
    }
}

// ---------------- CSR construction ------------------------------------------
__global__ void k_zero_cnt(int n) {
    int i = blockIdx.x * blockDim.x + threadIdx.x;
    if (i < n) g_cnt[i] = 0;
}

__global__ void k_hist(const int* __restrict__ rows, int e) {
    int i = blockIdx.x * blockDim.x + threadIdx.x;
    if (i < e) atomicAdd(&g_cnt[rows[i]], 1);
}

__global__ void __launch_bounds__(512) k_scanA(int n) {
    __shared__ int sh[512];
    int t = threadIdx.x;
    int i = blockIdx.x * 512 + t;
    int c = (i < n) ? g_cnt[i] : 0;
    sh[t] = c;
    __syncthreads();
    int val = c;
#pragma unroll
    for (int off = 1; off < 512; off <<= 1) {
        int tt = (t >= off) ? sh[t - off] : 0;
        __syncthreads();
        val += tt;
        sh[t] = val;
        __syncthreads();
    }
    if (i < n) g_rowstart[i] = val - c;
    if (t == 511) g_bsum[blockIdx.x] = val;
}

__global__ void __launch_bounds__(256) k_scanB(int nb) {
    __shared__ int sh[256];
    int t = threadIdx.x;
    int c = (t < nb) ? g_bsum[t] : 0;
    sh[t] = c;
    __syncthreads();
    int val = c;
#pragma unroll
    for (int off = 1; off < 256; off <<= 1) {
        int tt = (t >= off) ? sh[t - off] : 0;
        __syncthreads();
        val += tt;
        sh[t] = val;
        __syncthreads();
    }
    if (t < nb) g_boff[t] = val - c;
}

__global__ void k_scanC(int n) {
    int i = blockIdx.x * blockDim.x + threadIdx.x;
    if (i >= n) return;
    int s = g_rowstart[i] + g_boff[i >> 9];
    g_rowstart[i] = s;
    g_fill[i] = s;
}

__global__ void k_scatter(const int* __restrict__ rows,
                          const int* __restrict__ cols,
                          const float* __restrict__ vals, int e) {
    int i = blockIdx.x * blockDim.x + threadIdx.x;
    if (i >= e) return;
    int r = rows[i];
    int idx = atomicAdd(&g_fill[r], 1);
    g_epack[idx] = make_int2(cols[i], __float_as_int(vals[i]));
}

// ---------------- fused spmm1 + mid: agg over supp1, emit h (8-wide) -------
__global__ void __launch_bounds__(256)
k_spmm1mid(const float* __restrict__ b1, int n)
{
    __shared__ float sb1[NHID];
    if (threadIdx.x < NHID) sb1[threadIdx.x] = b1[threadIdx.x];
    __syncthreads();
    int r = blockIdx.x * blockDim.x + threadIdx.x;
    if (r >= n) return;

    const int start = g_rowstart[r];
    const int deg   = g_cnt[r];
    const int2* __restrict__ ep = g_epack + start;

    float a0 = 0.f, a1 = 0.f, a2 = 0.f, a3 = 0.f;
    float a4 = 0.f, a5 = 0.f, a6 = 0.f, a7 = 0.f;

    int j = 0;
    for (; j + 8 <= deg; j += 8) {
        // batch-load 8 edge records (independent LDGs -> MLP)
        int2 p[8];
#pragma unroll
        for (int q = 0; q < 8; q++) p[q] = ep[j + q];
#pragma unroll
        for (int q = 0; q < 8; q++) {
            const float4* __restrict__ s =
                reinterpret_cast<const float4*>(g_supp1 + (size_t)p[q].x * NHID);
            float4 u = s[0], w = s[1];
            float v = __int_as_float(p[q].y);
            a0 = fmaf(v, u.x, a0); a1 = fmaf(v, u.y, a1);
            a2 = fmaf(v, u.z, a2); a3 = fmaf(v, u.w, a3);
            a4 = fmaf(v, w.x, a4); a5 = fmaf(v, w.y, a5);
            a6 = fmaf(v, w.z, a6); a7 = fmaf(v, w.w, a7);
        }
    }
    for (; j < deg; j++) {
        int2 p = ep[j];
        const float4* __restrict__ s =
            reinterpret_cast<const float4*>(g_supp1 + (size_t)p.x * NHID);
        float4 u = s[0], w = s[1];
        float v = __int_as_float(p.y);
        a0 = fmaf(v, u.x, a0); a1 = fmaf(v, u.y, a1);
        a2 = fmaf(v, u.z, a2); a3 = fmaf(v, u.w, a3);
        a4 = fmaf(v, w.x, a4); a5 = fmaf(v, w.y, a5);
        a6 = fmaf(v, w.z, a6); a7 = fmaf(v, w.w, a7);
    }

    // epilogue: bias + relu + combine with xr -> h (8-wide)
    float ag[8] = {a0, a1, a2, a3, a4, a5, a6, a7};
    const float4* xr4 = reinterpret_cast<const float4*>(g_xr + (size_t)r * NHID);
    float4 x0 = xr4[0], x1 = xr4[1];
    float xr[8] = {x0.x, x0.y, x0.z, x0.w, x1.x, x1.y, x1.z, x1.w};

    float h[8];
#pragma unroll
    for (int k = 0; k < NHID; k++) {
        float t = fmaxf(ag[k] + sb1[k], 0.f);
        h[k] = 0.5f * (t + xr[k]);
    }
    float4* o = reinterpret_cast<float4*>(g_h + (size_t)r * NHID);
    o[0] = make_float4(h[0], h[1], h[2], h[3]);
    o[1] = make_float4(h[4], h[5], h[6], h[7]);
}

// ---- fused spmm2 (8-wide over h) + @W2 + b2 + log_softmax -----------------
// uses spmm(h)@W2 == spmm(h@W2): halves gather traffic and accumulators.
__global__ void __launch_bounds__(256)
k_spmm2final(const float* __restrict__ W2, const float* __restrict__ b2,
             float* __restrict__ out, int n)
{
    __shared__ float sW2[NHID * NCLASS];
    __shared__ float sb2[NCLASS];
    if (threadIdx.x < NHID * NCLASS) sW2[threadIdx.x] = W2[threadIdx.x];
    if (threadIdx.x < NCLASS)        sb2[threadIdx.x] = b2[threadIdx.x];
    __syncthreads();
    int r = blockIdx.x * blockDim.x + threadIdx.x;
    if (r >= n) return;

    const int start = g_rowstart[r];
    const int deg   = g_cnt[r];
    const int2* __restrict__ ep = g_epack + start;

    float a0 = 0.f, a1 = 0.f, a2 = 0.f, a3 = 0.f;
    float a4 = 0.f, a5 = 0.f, a6 = 0.f, a7 = 0.f;

    int j = 0;
    for (; j + 8 <= deg; j += 8) {
        int2 p[8];
#pragma unroll
        for (int q = 0; q < 8; q++) p[q] = ep[j + q];
#pragma unroll
        for (int q = 0; q < 8; q++) {
            const float4* __restrict__ s =
                reinterpret_cast<const float4*>(g_h + (size_t)p[q].x * NHID);
            float4 u = s[0], w = s[1];
            float v = __int_as_float(p[q].y);
            a0 = fmaf(v, u.x, a0); a1 = fmaf(v, u.y, a1);
            a2 = fmaf(v, u.z, a2); a3 = fmaf(v, u.w, a3);
            a4 = fmaf(v, w.x, a4); a5 = fmaf(v, w.y, a5);
            a6 = fmaf(v, w.z, a6); a7 = fmaf(v, w.w, a7);
        }
    }
    for (; j < deg; j++) {
        int2 p = ep[j];
        const float4* __restrict__ s =
            reinterpret_cast<const float4*>(g_h + (size_t)p.x * NHID);
        float4 u = s[0], w = s[1];
        float v = __int_as_float(p.y);
        a0 = fmaf(v, u.x, a0); a1 = fmaf(v, u.y, a1);
        a2 = fmaf(v, u.z, a2); a3 = fmaf(v, u.w, a3);
        a4 = fmaf(v, w.x, a4); a5 = fmaf(v, w.y, a5);
        a6 = fmaf(v, w.z, a6); a7 = fmaf(v, w.w, a7);
    }

    float ag[8] = {a0, a1, a2, a3, a4, a5, a6, a7};

    // tiny dense epilogue: v = ag @ W2 + b2
    float v[NCLASS];
#pragma unroll
    for (int q = 0; q < NCLASS; q++) v[q] = sb2[q];
#pragma unroll
    for (int k = 0; k < NHID; k++) {
        float hk = ag[k];
#pragma unroll
        for (int q = 0; q < NCLASS; q++) v[q] = fmaf(hk, sW2[k * NCLASS + q], v[q]);
    }

    float m = v[0];
#pragma unroll
    for (int q = 1; q < NCLASS; q++) m = fmaxf(m, v[q]);
    float s = 0.f;
#pragma unroll
    for (int q = 0; q < NCLASS; q++) s += expf(v[q] - m);
    float l = m + logf(s);

    float4* o = reinterpret_cast<float4*>(out + (size_t)r * NCLASS);
    o[0] = make_float4(v[0]  - l, v[1]  - l, v[2]  - l, v[3]  - l);
    o[1] = make_float4(v[4]  - l, v[5]  - l, v[6]  - l, v[7]  - l);
    o[2] = make_float4(v[8]  - l, v[9]  - l, v[10] - l, v[11] - l);
    o[3] = make_float4(v[12] - l, v[13] - l, v[14] - l, v[15] - l);
}

// ---------------- launch ----------------------------------------------------
extern "C" void kernel_launch(void* const* d_in, const int* in_sizes, int n_in,
                              void* d_out, int out_size)
{
    const float* x        = (const float*)d_in[0];
    const int*   adj_rows = (const int*)  d_in[1];
    const int*   adj_cols = (const int*)  d_in[2];
    const float* adj_vals = (const float*)d_in[3];
    const float* W1       = (const float*)d_in[4];
    const float* b1       = (const float*)d_in[5];
    const float* W2       = (const float*)d_in[6];
    const float* b2       = (const float*)d_in[7];
    const float* V        = (const float*)d_in[8];
    const float* gamma    = (const float*)d_in[9];
    const float* beta     = (const float*)d_in[10];
    float* out = (float*)d_out;

    const int n = in_sizes[0] / NFEAT;
    const int e = in_sizes[1];

    const int smem1 = K1_SMEM_FLOATS * (int)sizeof(float);
    cudaFuncSetAttribute(k1_transform, cudaFuncAttributeMaxDynamicSharedMemorySize, smem1);

    const int nbScan = (n + 511) / 512;

    // CSR build
    k_zero_cnt<<<(n + 255) / 256, 256>>>(n);
    k_hist<<<(e + 255) / 256, 256>>>(adj_rows, e);
    k_scanA<<<nbScan, 512>>>(n);
    k_scanB<<<1, 256>>>(nbScan);
    k_scanC<<<(n + 255) / 256, 256>>>(n);
    k_scatter<<<(e + 255) / 256, 256>>>(adj_rows, adj_cols, adj_vals, e);

    // node transform (independent of CSR; produces supp1 + xr)
    k1_transform<<<(n + 255) / 256, 256, smem1>>>(x, W1, V, gamma, beta, n);

    // fused spmm1 + mid -> h (8-wide)
    k_spmm1mid<<<(n + 255) / 256, 256>>>(b1, n);
    // fused spmm2 (8-wide) + @W2 + b2 + log_softmax -> out
    k_spmm2final<<<(n + 255) / 256, 256>>>(W2, b2, out, n);
}

// round 17
// speedup vs baseline: 1.0788x; 1.0006x over previous
#include <cuda_runtime.h>
#include <cuda_bf16.h>

// Problem constants (fixed shapes from reference)
#define NMAX   100000
#define EMAX   3200000
#define NFEAT  512
#define NHID   8
#define NCLASS 16

// ---------------- scratch (device globals; no allocation allowed) ----------
__device__ float g_supp1[NMAX * NHID];    // x @ W1
__device__ float g_xr   [NMAX * NHID];    // gamma*relu(0.5*(xv^2 - x2v2))+beta
__device__ float g_h    [NMAX * NHID];    // 0.5*(relu(agg1+b1)+xr)  (8-wide!)
__device__ int   g_cnt     [NMAX];        // row degree
__device__ int   g_rowstart[NMAX];        // CSR row start
__device__ int   g_fill    [NMAX];        // scatter cursor
__device__ int   g_bsum[256];             // scan block sums
__device__ int   g_boff[256];             // scanned block offsets
__device__ int2  g_epack[EMAX];           // packed (col, val-bits), CSR order

// ---------------- f32x2 packed-math helpers (Blackwell) --------------------
__device__ __forceinline__ unsigned long long pk2(float a, float b) {
    unsigned long long r;
    asm("mov.b64 %0, {%1, %2};" : "=l"(r) : "f"(a), "f"(b));
    return r;
}
__device__ __forceinline__ unsigned long long ffma2(unsigned long long a,
                                                    unsigned long long b,
                                                    unsigned long long c) {
    unsigned long long d;
    asm("fma.rn.f32x2 %0, %1, %2, %3;" : "=l"(d) : "l"(a), "l"(b), "l"(c));
    return d;
}
__device__ __forceinline__ void upk2(unsigned long long v, float& a, float& b) {
    asm("mov.b64 {%0, %1}, %2;" : "=f"(a), "=f"(b) : "l"(v));
}

// ---------------- kernel 1: fused node transform (unchanged, works) --------
#define KT 32
#define K1_WARPS 8
#define K1_SX_STRIDE 33
#define K1_SMEM_FLOATS (3 * NFEAT * NHID + K1_WARPS * 32 * K1_SX_STRIDE + 16)

__global__ void __launch_bounds__(256)
k1_transform(const float* __restrict__ x,
             const float* __restrict__ W1,
             const float* __restrict__ V,
             const float* __restrict__ gamma,
             const float* __restrict__ beta,
             int n)
{
    extern __shared__ __align__(16) float sm[];
    float* sW1 = sm;
    float* sV  = sm + NFEAT * NHID;
    float* sV2 = sm + 2 * NFEAT * NHID;
    float* sx  = sm + 3 * NFEAT * NHID;
    float* sgb = sx + K1_WARPS * 32 * K1_SX_STRIDE;

    int tid = threadIdx.x;
    for (int i = tid; i < NFEAT * NHID; i += blockDim.x) {
        float w = W1[i];  sW1[i] = w;
        float v = V[i];   sV[i]  = v;  sV2[i] = v * v;
    }
    if (tid < NHID) { sgb[tid] = gamma[tid]; sgb[NHID + tid] = beta[tid]; }
    __syncthreads();

    const int warp = tid >> 5, lane = tid & 31;
    float* sxw = sx + warp * (32 * K1_SX_STRIDE);
    const int nodeBase = blockIdx.x * 256 + warp * 32;
    const int myNode = nodeBase + lane;

    const ulonglong2* pW1 = reinterpret_cast<const ulonglong2*>(sW1);
    const ulonglong2* pV  = reinterpret_cast<const ulonglong2*>(sV);
    const ulonglong2* pQ  = reinterpret_cast<const ulonglong2*>(sV2);

    unsigned long long aW[4] = {0ull, 0ull, 0ull, 0ull};
    unsigned long long aX[4] = {0ull, 0ull, 0ull, 0ull};
    unsigned long long aQ[4] = {0ull, 0ull, 0ull, 0ull};

    const int r0 = lane >> 3;
    const int c0 = (lane & 7) * 4;

#pragma unroll 1
    for (int kt = 0; kt < NFEAT; kt += KT) {
#pragma unroll
        for (int i = 0; i < 8; i++) {
            int row = r0 + i * 4;
            int node = nodeBase + row;
            if (node >= n) node = n - 1;
            float4 v4 = *reinterpret_cast<const float4*>(x + (size_t)node * NFEAT + kt + c0);
            float* d = sxw + row * K1_SX_STRIDE + c0;
            d[0] = v4.x; d[1] = v4.y; d[2] = v4.z; d[3] = v4.w;
        }
        __syncwarp();
        const float* myx = sxw + lane * K1_SX_STRIDE;
#pragma unroll
        for (int kk = 0; kk < KT; kk++) {
            float xv = myx[kk];
            float x2 = xv * xv;
            unsigned long long xp  = pk2(xv, xv);
            unsigned long long x2p = pk2(x2, x2);
            int k2 = (kt + kk) * 2;
            ulonglong2 wa = pW1[k2], wb = pW1[k2 + 1];
            aW[0] = ffma2(xp, wa.x, aW[0]);  aW[1] = ffma2(xp, wa.y, aW[1]);
            aW[2] = ffma2(xp, wb.x, aW[2]);  aW[3] = ffma2(xp, wb.y, aW[3]);
            ulonglong2 va = pV[k2],  vb = pV[k2 + 1];
            aX[0] = ffma2(xp, va.x, aX[0]);  aX[1] = ffma2(xp, va.y, aX[1]);
            aX[2] = ffma2(xp, vb.x, aX[2]);  aX[3] = ffma2(xp, vb.y, aX[3]);
            ulonglong2 qa = pQ[k2],  qb = pQ[k2 + 1];
            aQ[0] = ffma2(x2p, qa.x, aQ[0]); aQ[1] = ffma2(x2p, qa.y, aQ[1]);
            aQ[2] = ffma2(x2p, qb.x, aQ[2]); aQ[3] = ffma2(x2p, qb.y, aQ[3]);
        }
        __syncwarp();
    }

    if (myNode < n) {
        float o[8], xvv[8], qq[8];
        upk2(aW[0], o[0], o[1]);   upk2(aW[1], o[2], o[3]);
        upk2(aW[2], o[4], o[5]);   upk2(aW[3], o[6], o[7]);
        upk2(aX[0], xvv[0], xvv[1]); upk2(aX[1], xvv[2], xvv[3]);
        upk2(aX[2], xvv[4], xvv[5]); upk2(aX[3], xvv[6], xvv[7]);
        upk2(aQ[0], qq[0], qq[1]);   upk2(aQ[1], qq[2], qq[3]);
        upk2(aQ[2], qq[4], qq[5]);   upk2(aQ[3], qq[6], qq[7]);

        float4* ds = reinterpret_cast<float4*>(g_supp1 + (size_t)myNode * NHID);
        ds[0] = make_float4(o[0], o[1], o[2], o[3]);
        ds[1] = make_float4(o[4], o[5], o[6], o[7]);

        float xr[8];
#pragma unroll
        for (int j = 0; j < NHID; j++) {
            float t = 0.5f * (xvv[j] * xvv[j] - qq[j]);
            t = fmaxf(t, 0.f);
            xr[j] = sgb[j] * t + sgb[NHID + j];
        }
        float4* dr = reinterpret_cast<float4*>(g_xr + (size_t)myNode * NHID);
        dr[0] = make_float4(xr[0], xr[1], xr[2], xr[3]);
        dr[1] = make_float4(xr[4], xr[5], xr[6], xr[7]);
    }
}

// ---------------- CSR construction ------------------------------------------
__global__ void k_zero_cnt(int n) {
    int i = blockIdx.x * blockDim.x + threadIdx.x;
    if (i < n) g_cnt[i] = 0;
}

__global__ void k_hist(const int* __restrict__ rows, int e) {
    int i = blockIdx.x * blockDim.x + threadIdx.x;
    if (i < e) atomicAdd(&g_cnt[rows[i]], 1);
}

__global__ void __launch_bounds__(512) k_scanA(int n) {
    __shared__ int sh[512];
    int t = threadIdx.x;
    int i = blockIdx.x * 512 + t;
    int c = (i < n) ? g_cnt[i] : 0;
    sh[t] = c;
    __syncthreads();
    int val = c;
#pragma unroll
    for (int off = 1; off < 512; off <<= 1) {
        int tt = (t >= off) ? sh[t - off] : 0;
        __syncthreads();
        val += tt;
        sh[t] = val;
        __syncthreads();
    }
    if (i < n) g_rowstart[i] = val - c;
    if (t == 511) g_bsum[blockIdx.x] = val;
}

__global__ void __launch_bounds__(256) k_scanB(int nb) {
    __shared__ int sh[256];
    int t = threadIdx.x;
    int c = (t < nb) ? g_bsum[t] : 0;
    sh[t] = c;
    __syncthreads();
    int val = c;
#pragma unroll
    for (int off = 1; off < 256; off <<= 1) {
        int tt = (t >= off) ? sh[t - off] : 0;
        __syncthreads();
        val += tt;
        sh[t] = val;
        __syncthreads();
    }
    if (t < nb) g_boff[t] = val - c;
}

__global__ void k_scanC(int n) {
    int i = blockIdx.x * blockDim.x + threadIdx.x;
    if (i >= n) return;
    int s = g_rowstart[i] + g_boff[i >> 9];
    g_rowstart[i] = s;
    g_fill[i] = s;
}

__global__ void k_scatter(const int* __restrict__ rows,
                          const int* __restrict__ cols,
                          const float* __restrict__ vals, int e) {
    int i = blockIdx.x * blockDim.x + threadIdx.x;
    if (i >= e) return;
    int r = rows[i];
    int idx = atomicAdd(&g_fill[r], 1);
    g_epack[idx] = make_int2(cols[i], __float_as_int(vals[i]));
}

// ---------------- fused spmm1 + mid: agg over supp1, emit h (8-wide) -------
__global__ void __launch_bounds__(256)
k_spmm1mid(const float* __restrict__ b1, int n)
{
    __shared__ float sb1[NHID];
    if (threadIdx.x < NHID) sb1[threadIdx.x] = b1[threadIdx.x];
    __syncthreads();
    int r = blockIdx.x * blockDim.x + threadIdx.x;
    if (r >= n) return;

    const int start = g_rowstart[r];
    const int deg   = g_cnt[r];
    const int2* __restrict__ ep = g_epack + start;

    float a0 = 0.f, a1 = 0.f, a2 = 0.f, a3 = 0.f;
    float a4 = 0.f, a5 = 0.f, a6 = 0.f, a7 = 0.f;

    int j = 0;
    for (; j + 8 <= deg; j += 8) {
        // batch-load 8 edge records (independent LDGs -> MLP)
        int2 p[8];
#pragma unroll
        for (int q = 0; q < 8; q++) p[q] = ep[j + q];
#pragma unroll
        for (int q = 0; q < 8; q++) {
            const float4* __restrict__ s =
                reinterpret_cast<const float4*>(g_supp1 + (size_t)p[q].x * NHID);
            float4 u = s[0], w = s[1];
            float v = __int_as_float(p[q].y);
            a0 = fmaf(v, u.x, a0); a1 = fmaf(v, u.y, a1);
            a2 = fmaf(v, u.z, a2); a3 = fmaf(v, u.w, a3);
            a4 = fmaf(v, w.x, a4); a5 = fmaf(v, w.y, a5);
            a6 = fmaf(v, w.z, a6); a7 = fmaf(v, w.w, a7);
        }
    }
    for (; j < deg; j++) {
        int2 p = ep[j];
        const float4* __restrict__ s =
            reinterpret_cast<const float4*>(g_supp1 + (size_t)p.x * NHID);
        float4 u = s[0], w = s[1];
        float v = __int_as_float(p.y);
        a0 = fmaf(v, u.x, a0); a1 = fmaf(v, u.y, a1);
        a2 = fmaf(v, u.z, a2); a3 = fmaf(v, u.w, a3);
        a4 = fmaf(v, w.x, a4); a5 = fmaf(v, w.y, a5);
        a6 = fmaf(v, w.z, a6); a7 = fmaf(v, w.w, a7);
    }

    // epilogue: bias + relu + combine with xr -> h (8-wide)
    float ag[8] = {a0, a1, a2, a3, a4, a5, a6, a7};
    const float4* xr4 = reinterpret_cast<const float4*>(g_xr + (size_t)r * NHID);
    float4 x0 = xr4[0], x1 = xr4[1];
    float xr[8] = {x0.x, x0.y, x0.z, x0.w, x1.x, x1.y, x1.z, x1.w};

    float h[8];
#pragma unroll
    for (int k = 0; k < NHID; k++) {
        float t = fmaxf(ag[k] + sb1[k], 0.f);
        h[k] = 0.5f * (t + xr[k]);
    }
    float4* o = reinterpret_cast<float4*>(g_h + (size_t)r * NHID);
    o[0] = make_float4(h[0], h[1], h[2], h[3]);
    o[1] = make_float4(h[4], h[5], h[6], h[7]);
}

// ---- fused spmm2 (8-wide over h) + @W2 + b2 + log_softmax -----------------
// uses spmm(h)@W2 == spmm(h@W2): halves gather traffic and accumulators.
__global__ void __launch_bounds__(256)
k_spmm2final(const float* __restrict__ W2, const float* __restrict__ b2,
             float* __restrict__ out, int n)
{
    __shared__ float sW2[NHID * NCLASS];
    __shared__ float sb2[NCLASS];
    if (threadIdx.x < NHID * NCLASS) sW2[threadIdx.x] = W2[threadIdx.x];
    if (threadIdx.x < NCLASS)        sb2[threadIdx.x] = b2[threadIdx.x];
    __syncthreads();
    int r = blockIdx.x * blockDim.x + threadIdx.x;
    if (r >= n) return;

    const int start = g_rowstart[r];
    const int deg   = g_cnt[r];
    const int2* __restrict__ ep = g_epack + start;

    float a0 = 0.f, a1 = 0.f, a2 = 0.f, a3 = 0.f;
    float a4 = 0.f, a5 = 0.f, a6 = 0.f, a7 = 0.f;

    int j = 0;
    for (; j + 8 <= deg; j += 8) {
        int2 p[8];
#pragma unroll
        for (int q = 0; q < 8; q++) p[q] = ep[j + q];
#pragma unroll
        for (int q = 0; q < 8; q++) {
            const float4* __restrict__ s =
                reinterpret_cast<const float4*>(g_h + (size_t)p[q].x * NHID);
            float4 u = s[0], w = s[1];
            float v = __int_as_float(p[q].y);
            a0 = fmaf(v, u.x, a0); a1 = fmaf(v, u.y, a1);
            a2 = fmaf(v, u.z, a2); a3 = fmaf(v, u.w, a3);
            a4 = fmaf(v, w.x, a4); a5 = fmaf(v, w.y, a5);
            a6 = fmaf(v, w.z, a6); a7 = fmaf(v, w.w, a7);
        }
    }
    for (; j < deg; j++) {
        int2 p = ep[j];
        const float4* __restrict__ s =
            reinterpret_cast<const float4*>(g_h + (size_t)p.x * NHID);
        float4 u = s[0], w = s[1];
        float v = __int_as_float(p.y);
        a0 = fmaf(v, u.x, a0); a1 = fmaf(v, u.y, a1);
        a2 = fmaf(v, u.z, a2); a3 = fmaf(v, u.w, a3);
        a4 = fmaf(v, w.x, a4); a5 = fmaf(v, w.y, a5);
        a6 = fmaf(v, w.z, a6); a7 = fmaf(v, w.w, a7);
    }

    float ag[8] = {a0, a1, a2, a3, a4, a5, a6, a7};

    // tiny dense epilogue: v = ag @ W2 + b2
    float v[NCLASS];
#pragma unroll
    for (int q = 0; q < NCLASS; q++) v[q] = sb2[q];
#pragma unroll
    for (int k = 0; k < NHID; k++) {
        float hk = ag[k];
#pragma unroll
        for (int q = 0; q < NCLASS; q++) v[q] = fmaf(hk, sW2[k * NCLASS + q], v[q]);
    }

    float m = v[0];
#pragma unroll
    for (int q = 1; q < NCLASS; q++) m = fmaxf(m, v[q]);
    float s = 0.f;
#pragma unroll
    for (int q = 0; q < NCLASS; q++) s += expf(v[q] - m);
    float l = m + logf(s);

    float4* o = reinterpret_cast<float4*>(out + (size_t)r * NCLASS);
    o[0] = make_float4(v[0]  - l, v[1]  - l, v[2]  - l, v[3]  - l);
    o[1] = make_float4(v[4]  - l, v[5]  - l, v[6]  - l, v[7]  - l);
    o[2] = make_float4(v[8]  - l, v[9]  - l, v[10] - l, v[11] - l);
    o[3] = make_float4(v[12] - l, v[13] - l, v[14] - l, v[15] - l);
}

// ---------------- launch ----------------------------------------------------
extern "C" void kernel_launch(void* const* d_in, const int* in_sizes, int n_in,
                              void* d_out, int out_size)
{
    const float* x        = (const float*)d_in[0];
    const int*   adj_rows = (const int*)  d_in[1];
    const int*   adj_cols = (const int*)  d_in[2];
    const float* adj_vals = (const float*)d_in[3];
    const float* W1       = (const float*)d_in[4];
    const float* b1       = (const float*)d_in[5];
    const float* W2       = (const float*)d_in[6];
    const float* b2       = (const float*)d_in[7];
    const float* V        = (const float*)d_in[8];
    const float* gamma    = (const float*)d_in[9];
    const float* beta     = (const float*)d_in[10];
    float* out = (float*)d_out;

    const int n = in_sizes[0] / NFEAT;
    const int e = in_sizes[1];

    const int smem1 = K1_SMEM_FLOATS * (int)sizeof(float);
    cudaFuncSetAttribute(k1_transform, cudaFuncAttributeMaxDynamicSharedMemorySize, smem1);

    const int nbScan = (n + 511) / 512;

    // CSR build
    k_zero_cnt<<<(n + 255) / 256, 256>>>(n);
    k_hist<<<(e + 255) / 256, 256>>>(adj_rows, e);
    k_scanA<<<nbScan, 512>>>(n);
    k_scanB<<<1, 256>>>(nbScan);
    k_scanC<<<(n + 255) / 256, 256>>>(n);
    k_scatter<<<(e + 255) / 256, 256>>>(adj_rows, adj_cols, adj_vals, e);

    // node transform (independent of CSR; produces supp1 + xr)
    k1_transform<<<(n + 255) / 256, 256, smem1>>>(x, W1, V, gamma, beta, n);

    // fused spmm1 + mid -> h (8-wide)
    k_spmm1mid<<<(n + 255) / 256, 256>>>(b1, n);
    // fused spmm2 (8-wide) + @W2 + b2 + log_softmax -> out
    k_spmm2final<<<(n + 255) / 256, 256>>>(W2, b2, out, n);
}